// round 5
// baseline (speedup 1.0000x reference)
#include <cuda_runtime.h>
#include <math.h>
#include <stdint.h>

// ---------------- problem constants ----------------
#define T_TOK 2048
#define HDIM  2048
#define FB    8192
#define NE    8
#define FE    1024
#define TOPK  2
#define NPAIR (T_TOK * TOPK)

// ---------------- scratch ----------------
__device__ float g_G   [(size_t)T_TOK * FB];
__device__ float g_Hb  [(size_t)T_TOK * FB];
__device__ float g_base[(size_t)T_TOK * HDIM];
__device__ float g_EG  [(size_t)NPAIR * FE];
__device__ float g_HE  [(size_t)NPAIR * FE];
__device__ float g_pout[(size_t)NPAIR * HDIM];
__device__ int   g_cnt[NE];
__device__ int   g_off[NE + 1];
__device__ int   g_cur[NE];
__device__ int   g_tokexp[T_TOK * TOPK];
__device__ float g_tokw  [T_TOK * TOPK];
__device__ int   g_pairtok[NPAIR];
__device__ float g_pairw  [NPAIR];
__device__ int   g_tokpair[T_TOK * TOPK];
__device__ float g_c[T_TOK];

// ---------------- small kernels (fp32-exact routing) ----------------
__global__ void zero_counts_kernel() {
    int i = threadIdx.x;
    if (i < NE) g_cnt[i] = 0;
}

__global__ void router_kernel(const float* __restrict__ x,
                              const float* __restrict__ rw,
                              const float* __restrict__ alpha) {
    int t = blockIdx.x;
    int tid = threadIdx.x;
    int w = tid >> 5;
    int lane = tid & 31;
    __shared__ float lg[NE];

    float s = 0.f;
    const float* xr = x + (size_t)t * HDIM;
    const float* wr = rw + (size_t)w * HDIM;
    for (int h = lane; h < HDIM; h += 32) s += xr[h] * wr[h];
    #pragma unroll
    for (int o = 16; o > 0; o >>= 1) s += __shfl_down_sync(0xffffffffu, s, o);
    if (lane == 0) lg[w] = s;
    __syncthreads();

    if (tid == 0) {
        float v0 = -1e30f, v1 = -1e30f;
        int i0 = 0, i1 = 0;
        #pragma unroll
        for (int e = 0; e < NE; e++) {
            float v = lg[e];
            if (v > v0) { v1 = v0; i1 = i0; v0 = v; i0 = e; }
            else if (v > v1) { v1 = v; i1 = e; }
        }
        float e1 = expf(v1 - v0);
        float inv = 1.f / (1.f + e1);
        float wa0 = inv * alpha[i0];
        float wa1 = e1 * inv * alpha[i1];
        g_tokexp[2 * t + 0] = i0;
        g_tokexp[2 * t + 1] = i1;
        g_tokw[2 * t + 0] = wa0;
        g_tokw[2 * t + 1] = wa1;
        g_c[t] = 1.f - wa0 - wa1;
        atomicAdd(&g_cnt[i0], 1);
        atomicAdd(&g_cnt[i1], 1);
    }
}

__global__ void scan_kernel() {
    if (threadIdx.x == 0) {
        int acc = 0;
        for (int e = 0; e < NE; e++) {
            g_off[e] = acc;
            g_cur[e] = acc;
            acc += g_cnt[e];
        }
        g_off[NE] = acc;
    }
}

__global__ void scatter_kernel() {
    int t = blockIdx.x * blockDim.x + threadIdx.x;
    if (t >= T_TOK) return;
    #pragma unroll
    for (int s = 0; s < TOPK; s++) {
        int e = g_tokexp[2 * t + s];
        int pos = atomicAdd(&g_cur[e], 1);
        g_pairtok[pos] = t;
        g_pairw[pos] = g_tokw[2 * t + s];
        g_tokpair[2 * t + s] = pos;
    }
}

// ---------------- helpers ----------------
__device__ __forceinline__ uint32_t smem_u32(const void* p) {
    uint32_t a;
    asm("{ .reg .u64 t; cvta.to.shared.u64 t, %1; cvt.u32.u64 %0, t; }" : "=r"(a) : "l"(p));
    return a;
}
__device__ __forceinline__ uint32_t f2tf32(float f) {
    uint32_t u;
    asm("cvt.rna.tf32.f32 %0, %1;" : "=r"(u) : "f"(f));
    return u;
}
__device__ __forceinline__ void mma_tf32(float c[4], const uint32_t a[4], const uint32_t b[2]) {
    asm volatile(
        "mma.sync.aligned.m16n8k8.row.col.f32.tf32.tf32.f32 "
        "{%0,%1,%2,%3}, {%4,%5,%6,%7}, {%8,%9}, {%0,%1,%2,%3};\n"
        : "+f"(c[0]), "+f"(c[1]), "+f"(c[2]), "+f"(c[3])
        : "r"(a[0]), "r"(a[1]), "r"(a[2]), "r"(a[3]), "r"(b[0]), "r"(b[1]));
}
#define LDSM_X4(r, addr) \
    asm volatile("ldmatrix.sync.aligned.m8n8.x4.shared.b16 {%0,%1,%2,%3}, [%4];" \
        : "=r"((r)[0]), "=r"((r)[1]), "=r"((r)[2]), "=r"((r)[3]) : "r"(addr))
#define LDSM_X2(r, addr) \
    asm volatile("ldmatrix.sync.aligned.m8n8.x2.shared.b16 {%0,%1}, [%2];" \
        : "=r"((r)[0]), "=r"((r)[1]) : "r"(addr))

// ---------------- mma.sync tf32 NT GEMM with ldmatrix + 2-stage pipeline ----------
// C[m,n] = sum_k A[m,k]*B[n,k]; tile BM=BN=128, BK=32.
// Tiles stored swizzled: elem(row, c) at byte row*128 + (((c>>2) ^ (row&7))<<4) + (c&3)*4.
// MODE 0: C=acc; MODE 1: C=silu(aux)*acc; MODE 2: C=acc*rowscale[row]
// GROUPED: blockIdx.z = expert, rows in [off[e], off[e+1]), B += e*N*K
// GATHER:  A row = gidx[global_row]
#define TILE_B 16384                 // one 128x32 f32 tile
#define STAGE_B (2 * TILE_B)         // A + B per stage
#define SMEM_TOTAL (2 * STAGE_B)     // 64KB

template <int MODE, bool GROUPED, bool GATHER>
__global__ void __launch_bounds__(256)
gemm_mma(const float* __restrict__ A,
         const float* __restrict__ Bb,
         float* __restrict__ C,
         const float* __restrict__ aux,
         const float* __restrict__ rowscale,
         const int* __restrict__ offs,
         const int* __restrict__ gidx,
         int M, int N, int K) {
    extern __shared__ __align__(128) char smem[];

    int rstart, rend;
    const float* B = Bb;
    if (GROUPED) {
        int e = blockIdx.z;
        rstart = offs[e];
        rend = offs[e + 1];
        B += (size_t)e * N * K;
    } else {
        rstart = 0;
        rend = M;
    }
    int rowBase = rstart + blockIdx.y * 128;
    if (rowBase >= rend) return;
    int colBase = blockIdx.x * 128;

    uint32_t sb = smem_u32(smem);
    int tid = threadIdx.x;
    int wid = tid >> 5, lane = tid & 31;
    int warp_m = wid & 1;     // 2 warps over M (64 rows each)
    int warp_n = wid >> 1;    // 4 warps over N (32 cols each)
    int g = lane >> 2, tg = lane & 3;

    // ---- loader assignments (4 float4 per thread per tile) ----
    int lrow[4], lc4[4], aidx[4];
    uint32_t soff[4];
    bool aval[4];
    #pragma unroll
    for (int j = 0; j < 4; j++) {
        int f = tid + j * 256;
        lrow[j] = f >> 3;
        lc4[j] = f & 7;
        soff[j] = (uint32_t)(lrow[j] * 128 + (((lc4[j]) ^ (lrow[j] & 7)) << 4));
        int grow = rowBase + lrow[j];
        aval[j] = (grow < rend);
        aidx[j] = aval[j] ? (GATHER ? gidx[grow] : grow) : 0;
    }

    // ---- ldmatrix address components ----
    int la7 = lane & 7;
    int lahi = (lane >> 3) & 1;       // A: row +8 selector
    int lav = lane >> 4;              // A: k-chunk +1 selector
    int bhi = (lane >> 3) & 1;        // B: k-chunk selector (lanes 0-15 used)
    uint32_t a_row0 = (uint32_t)(warp_m * 64 + la7 + lahi * 8);
    uint32_t b_row0 = (uint32_t)(warp_n * 32 + la7);

    float acc[4][4][4];
    #pragma unroll
    for (int mt = 0; mt < 4; mt++)
        #pragma unroll
        for (int nt = 0; nt < 4; nt++)
            #pragma unroll
            for (int r = 0; r < 4; r++) acc[mt][nt][r] = 0.f;

    int NC = K / 32;
    float4 pa[4], pb[4];

    // ---- prologue: LDG chunk0, STS chunk0 -> stage0, LDG chunk1 ----
    #pragma unroll
    for (int j = 0; j < 4; j++)
        pa[j] = aval[j] ? *reinterpret_cast<const float4*>(A + (size_t)aidx[j] * K + lc4[j] * 4)
                        : make_float4(0.f, 0.f, 0.f, 0.f);
    #pragma unroll
    for (int j = 0; j < 4; j++)
        pb[j] = *reinterpret_cast<const float4*>(B + (size_t)(colBase + lrow[j]) * K + lc4[j] * 4);

    {
        uint32_t abase = sb, bbase = sb + TILE_B;
        #pragma unroll
        for (int j = 0; j < 4; j++) {
            uint4 v = make_uint4(f2tf32(pa[j].x), f2tf32(pa[j].y), f2tf32(pa[j].z), f2tf32(pa[j].w));
            asm volatile("st.shared.v4.b32 [%0], {%1,%2,%3,%4};"
                         :: "r"(abase + soff[j]), "r"(v.x), "r"(v.y), "r"(v.z), "r"(v.w) : "memory");
        }
        #pragma unroll
        for (int j = 0; j < 4; j++) {
            uint4 v = make_uint4(f2tf32(pb[j].x), f2tf32(pb[j].y), f2tf32(pb[j].z), f2tf32(pb[j].w));
            asm volatile("st.shared.v4.b32 [%0], {%1,%2,%3,%4};"
                         :: "r"(bbase + soff[j]), "r"(v.x), "r"(v.y), "r"(v.z), "r"(v.w) : "memory");
        }
    }
    if (NC > 1) {
        #pragma unroll
        for (int j = 0; j < 4; j++)
            pa[j] = aval[j] ? *reinterpret_cast<const float4*>(A + (size_t)aidx[j] * K + 32 + lc4[j] * 4)
                            : make_float4(0.f, 0.f, 0.f, 0.f);
        #pragma unroll
        for (int j = 0; j < 4; j++)
            pb[j] = *reinterpret_cast<const float4*>(B + (size_t)(colBase + lrow[j]) * K + 32 + lc4[j] * 4);
    }
    __syncthreads();

    // ---- mainloop ----
    for (int i = 0; i < NC; i++) {
        int s = i & 1;

        // STS chunk i+1 into other stage (regs loaded last iter), then prefetch i+2
        if (i + 1 < NC) {
            uint32_t abase = sb + (s ^ 1) * STAGE_B;
            uint32_t bbase = abase + TILE_B;
            #pragma unroll
            for (int j = 0; j < 4; j++) {
                uint4 v = make_uint4(f2tf32(pa[j].x), f2tf32(pa[j].y), f2tf32(pa[j].z), f2tf32(pa[j].w));
                asm volatile("st.shared.v4.b32 [%0], {%1,%2,%3,%4};"
                             :: "r"(abase + soff[j]), "r"(v.x), "r"(v.y), "r"(v.z), "r"(v.w) : "memory");
            }
            #pragma unroll
            for (int j = 0; j < 4; j++) {
                uint4 v = make_uint4(f2tf32(pb[j].x), f2tf32(pb[j].y), f2tf32(pb[j].z), f2tf32(pb[j].w));
                asm volatile("st.shared.v4.b32 [%0], {%1,%2,%3,%4};"
                             :: "r"(bbase + soff[j]), "r"(v.x), "r"(v.y), "r"(v.z), "r"(v.w) : "memory");
            }
            if (i + 2 < NC) {
                int k0 = (i + 2) * 32;
                #pragma unroll
                for (int j = 0; j < 4; j++)
                    pa[j] = aval[j] ? *reinterpret_cast<const float4*>(A + (size_t)aidx[j] * K + k0 + lc4[j] * 4)
                                    : make_float4(0.f, 0.f, 0.f, 0.f);
                #pragma unroll
                for (int j = 0; j < 4; j++)
                    pb[j] = *reinterpret_cast<const float4*>(B + (size_t)(colBase + lrow[j]) * K + k0 + lc4[j] * 4);
            }
        }

        // compute on stage s
        uint32_t abase = sb + s * STAGE_B;
        uint32_t bbase = abase + TILE_B;
        #pragma unroll
        for (int ks = 0; ks < 4; ks++) {
            uint32_t af[4][4], bf[4][2];
            #pragma unroll
            for (int mt = 0; mt < 4; mt++) {
                uint32_t addr = abase + (a_row0 + mt * 16) * 128 +
                                ((uint32_t)((ks * 2 + lav) ^ la7) << 4);
                LDSM_X4(af[mt], addr);
            }
            #pragma unroll
            for (int nt = 0; nt < 4; nt++) {
                uint32_t addr = bbase + (b_row0 + (uint32_t)(nt * 8)) * 128 +
                                ((uint32_t)((ks * 2 + bhi) ^ la7) << 4);
                LDSM_X2(bf[nt], addr);
            }
            #pragma unroll
            for (int mt = 0; mt < 4; mt++)
                #pragma unroll
                for (int nt = 0; nt < 4; nt++)
                    mma_tf32(acc[mt][nt], af[mt], bf[nt]);
        }
        __syncthreads();
    }

    // ---- epilogue: fragment -> float2 stores ----
    #pragma unroll
    for (int mt = 0; mt < 4; mt++) {
        #pragma unroll
        for (int half = 0; half < 2; half++) {
            int grow = rowBase + warp_m * 64 + mt * 16 + g + half * 8;
            if (grow >= rend) continue;
            float rs = (MODE == 2) ? rowscale[grow] : 0.f;
            #pragma unroll
            for (int nt = 0; nt < 4; nt++) {
                int col = colBase + warp_n * 32 + nt * 8 + tg * 2;
                size_t idx = (size_t)grow * N + col;
                float v0 = acc[mt][nt][half * 2 + 0];
                float v1 = acc[mt][nt][half * 2 + 1];
                float2 r;
                if (MODE == 0) {
                    r = make_float2(v0, v1);
                } else if (MODE == 1) {
                    float2 gg = *reinterpret_cast<const float2*>(aux + idx);
                    float s0 = gg.x / (1.f + __expf(-gg.x));
                    float s1 = gg.y / (1.f + __expf(-gg.y));
                    r = make_float2(s0 * v0, s1 * v1);
                } else {
                    r = make_float2(rs * v0, rs * v1);
                }
                *reinterpret_cast<float2*>(C + idx) = r;
            }
        }
    }
}

// ---------------- combine ----------------
__global__ void combine_kernel(float* __restrict__ out) {
    int t = blockIdx.x;
    int i = threadIdx.x;  // 0..511 (H/4)
    int p0 = g_tokpair[2 * t + 0];
    int p1 = g_tokpair[2 * t + 1];
    float ct = g_c[t];
    const float4* b4 = reinterpret_cast<const float4*>(g_base) + (size_t)t * (HDIM / 4);
    const float4* q0 = reinterpret_cast<const float4*>(g_pout) + (size_t)p0 * (HDIM / 4);
    const float4* q1 = reinterpret_cast<const float4*>(g_pout) + (size_t)p1 * (HDIM / 4);
    float4 b = b4[i], a0 = q0[i], a1 = q1[i];
    float4 r;
    r.x = ct * b.x + a0.x + a1.x;
    r.y = ct * b.y + a0.y + a1.y;
    r.z = ct * b.z + a0.z + a1.z;
    r.w = ct * b.w + a0.w + a1.w;
    reinterpret_cast<float4*>(out)[(size_t)t * (HDIM / 4) + i] = r;
}

// ---------------- launch ----------------
extern "C" void kernel_launch(void* const* d_in, const int* in_sizes, int n_in,
                              void* d_out, int out_size) {
    const float* x   = (const float*)d_in[0];
    const float* wg  = (const float*)d_in[1];
    const float* wu  = (const float*)d_in[2];
    const float* wd  = (const float*)d_in[3];
    const float* rw  = (const float*)d_in[4];
    const float* weg = (const float*)d_in[5];
    const float* weu = (const float*)d_in[6];
    const float* wed = (const float*)d_in[7];
    const float* alp = (const float*)d_in[8];
    float* out = (float*)d_out;

    float *pG, *pHb, *pBase, *pEG, *pHE, *pPout, *pPairw;
    int *pOff, *pPairtok;
    cudaGetSymbolAddress((void**)&pG, g_G);
    cudaGetSymbolAddress((void**)&pHb, g_Hb);
    cudaGetSymbolAddress((void**)&pBase, g_base);
    cudaGetSymbolAddress((void**)&pEG, g_EG);
    cudaGetSymbolAddress((void**)&pHE, g_HE);
    cudaGetSymbolAddress((void**)&pPout, g_pout);
    cudaGetSymbolAddress((void**)&pPairw, g_pairw);
    cudaGetSymbolAddress((void**)&pOff, g_off);
    cudaGetSymbolAddress((void**)&pPairtok, g_pairtok);

    cudaFuncSetAttribute(gemm_mma<0, false, false>, cudaFuncAttributeMaxDynamicSharedMemorySize, SMEM_TOTAL);
    cudaFuncSetAttribute(gemm_mma<1, false, false>, cudaFuncAttributeMaxDynamicSharedMemorySize, SMEM_TOTAL);
    cudaFuncSetAttribute(gemm_mma<0, true, true>,  cudaFuncAttributeMaxDynamicSharedMemorySize, SMEM_TOTAL);
    cudaFuncSetAttribute(gemm_mma<1, true, true>,  cudaFuncAttributeMaxDynamicSharedMemorySize, SMEM_TOTAL);
    cudaFuncSetAttribute(gemm_mma<2, true, false>, cudaFuncAttributeMaxDynamicSharedMemorySize, SMEM_TOTAL);

    // 1) routing (fp32-exact)
    zero_counts_kernel<<<1, 32>>>();
    router_kernel<<<T_TOK, 256>>>(x, rw, alp);
    scan_kernel<<<1, 1>>>();
    scatter_kernel<<<T_TOK / 256, 256>>>();

    // 2) base MLP
    dim3 gBaseFF(FB / 128, T_TOK / 128, 1);
    gemm_mma<0, false, false><<<gBaseFF, 256, SMEM_TOTAL>>>(x, wg, pG, nullptr, nullptr, nullptr, nullptr,
                                                            T_TOK, FB, HDIM);
    gemm_mma<1, false, false><<<gBaseFF, 256, SMEM_TOTAL>>>(x, wu, pHb, pG, nullptr, nullptr, nullptr,
                                                            T_TOK, FB, HDIM);
    dim3 gBaseDown(HDIM / 128, T_TOK / 128, 1);
    gemm_mma<0, false, false><<<gBaseDown, 256, SMEM_TOTAL>>>(pHb, wd, pBase, nullptr, nullptr, nullptr, nullptr,
                                                              T_TOK, HDIM, FB);

    // 3) expert MLPs (grouped, gathered)
    dim3 gExpFF(FE / 128, 16, NE);
    gemm_mma<0, true, true><<<gExpFF, 256, SMEM_TOTAL>>>(x, weg, pEG, nullptr, nullptr, pOff, pPairtok,
                                                         NPAIR, FE, HDIM);
    gemm_mma<1, true, true><<<gExpFF, 256, SMEM_TOTAL>>>(x, weu, pHE, pEG, nullptr, pOff, pPairtok,
                                                         NPAIR, FE, HDIM);
    dim3 gExpDown(HDIM / 128, 16, NE);
    gemm_mma<2, true, false><<<gExpDown, 256, SMEM_TOTAL>>>(pHE, wed, pPout, nullptr, pPairw, pOff, nullptr,
                                                            NPAIR, HDIM, FE);

    // 4) combine
    combine_kernel<<<T_TOK, HDIM / 4>>>(out);
}

// round 6
// speedup vs baseline: 1.3472x; 1.3472x over previous
#include <cuda_runtime.h>
#include <math.h>
#include <stdint.h>

// ---------------- problem constants ----------------
#define T_TOK 2048
#define HDIM  2048
#define FB    8192
#define NE    8
#define FE    1024
#define TOPK  2
#define NPAIR (T_TOK * TOPK)

// ---------------- scratch ----------------
__device__ float g_G   [(size_t)T_TOK * FB];
__device__ float g_Hb  [(size_t)T_TOK * FB];
__device__ float g_base[(size_t)T_TOK * HDIM];
__device__ float g_EG  [(size_t)NPAIR * FE];
__device__ float g_HE  [(size_t)NPAIR * FE];
__device__ float g_pout[(size_t)NPAIR * HDIM];
__device__ int   g_cnt[NE];
__device__ int   g_off[NE + 1];
__device__ int   g_cur[NE];
__device__ int   g_tokexp[T_TOK * TOPK];
__device__ float g_tokw  [T_TOK * TOPK];
__device__ int   g_pairtok[NPAIR];
__device__ float g_pairw  [NPAIR];
__device__ int   g_tokpair[T_TOK * TOPK];
__device__ float g_c[T_TOK];

// ---------------- small kernels (fp32-exact routing) ----------------
__global__ void zero_counts_kernel() {
    int i = threadIdx.x;
    if (i < NE) g_cnt[i] = 0;
}

__global__ void router_kernel(const float* __restrict__ x,
                              const float* __restrict__ rw,
                              const float* __restrict__ alpha) {
    int t = blockIdx.x;
    int tid = threadIdx.x;
    int w = tid >> 5;
    int lane = tid & 31;
    __shared__ float lg[NE];

    float s = 0.f;
    const float* xr = x + (size_t)t * HDIM;
    const float* wr = rw + (size_t)w * HDIM;
    for (int h = lane; h < HDIM; h += 32) s += xr[h] * wr[h];
    #pragma unroll
    for (int o = 16; o > 0; o >>= 1) s += __shfl_down_sync(0xffffffffu, s, o);
    if (lane == 0) lg[w] = s;
    __syncthreads();

    if (tid == 0) {
        float v0 = -1e30f, v1 = -1e30f;
        int i0 = 0, i1 = 0;
        #pragma unroll
        for (int e = 0; e < NE; e++) {
            float v = lg[e];
            if (v > v0) { v1 = v0; i1 = i0; v0 = v; i0 = e; }
            else if (v > v1) { v1 = v; i1 = e; }
        }
        float e1 = expf(v1 - v0);
        float inv = 1.f / (1.f + e1);
        float wa0 = inv * alpha[i0];
        float wa1 = e1 * inv * alpha[i1];
        g_tokexp[2 * t + 0] = i0;
        g_tokexp[2 * t + 1] = i1;
        g_tokw[2 * t + 0] = wa0;
        g_tokw[2 * t + 1] = wa1;
        g_c[t] = 1.f - wa0 - wa1;
        atomicAdd(&g_cnt[i0], 1);
        atomicAdd(&g_cnt[i1], 1);
    }
}

__global__ void scan_kernel() {
    if (threadIdx.x == 0) {
        int acc = 0;
        for (int e = 0; e < NE; e++) {
            g_off[e] = acc;
            g_cur[e] = acc;
            acc += g_cnt[e];
        }
        g_off[NE] = acc;
    }
}

__global__ void scatter_kernel() {
    int t = blockIdx.x * blockDim.x + threadIdx.x;
    if (t >= T_TOK) return;
    #pragma unroll
    for (int s = 0; s < TOPK; s++) {
        int e = g_tokexp[2 * t + s];
        int pos = atomicAdd(&g_cur[e], 1);
        g_pairtok[pos] = t;
        g_pairw[pos] = g_tokw[2 * t + s];
        g_tokpair[2 * t + s] = pos;
    }
}

// ---------------- helpers ----------------
__device__ __forceinline__ uint32_t smem_u32(const void* p) {
    uint32_t a;
    asm("{ .reg .u64 t; cvta.to.shared.u64 t, %1; cvt.u32.u64 %0, t; }" : "=r"(a) : "l"(p));
    return a;
}
__device__ __forceinline__ uint32_t f2tf32(uint32_t fbits) {
    uint32_t u;
    asm("cvt.rna.tf32.f32 %0, %1;" : "=r"(u) : "r"(fbits));
    return u;
}
__device__ __forceinline__ void mma_tf32(float c[4], const uint32_t a[4], const uint32_t b[2]) {
    asm volatile(
        "mma.sync.aligned.m16n8k8.row.col.f32.tf32.tf32.f32 "
        "{%0,%1,%2,%3}, {%4,%5,%6,%7}, {%8,%9}, {%0,%1,%2,%3};\n"
        : "+f"(c[0]), "+f"(c[1]), "+f"(c[2]), "+f"(c[3])
        : "r"(a[0]), "r"(a[1]), "r"(a[2]), "r"(a[3]), "r"(b[0]), "r"(b[1]));
}
#define LDSM_X4(r, addr) \
    asm volatile("ldmatrix.sync.aligned.m8n8.x4.shared.b16 {%0,%1,%2,%3}, [%4];" \
        : "=r"((r)[0]), "=r"((r)[1]), "=r"((r)[2]), "=r"((r)[3]) : "r"(addr))
#define LDSM_X2(r, addr) \
    asm volatile("ldmatrix.sync.aligned.m8n8.x2.shared.b16 {%0,%1}, [%2];" \
        : "=r"((r)[0]), "=r"((r)[1]) : "r"(addr))
#define CP_ASYNC16(dst, src, sz) \
    asm volatile("cp.async.cg.shared.global [%0], [%1], 16, %2;" \
        :: "r"(dst), "l"(src), "r"(sz) : "memory")
#define CP_COMMIT() asm volatile("cp.async.commit_group;" ::: "memory")
#define CP_WAIT1()  asm volatile("cp.async.wait_group 1;" ::: "memory")

// ---------------- cp.async 3-stage tf32 GEMM: C[m,n] = sum_k A[m,k]*B[n,k] --------
// Tile BM=BN=128, BK=32 (128B rows). Raw fp32 in smem, swizzled; cvt.rna in fragments.
// Swizzle: elem(row, c) at byte row*128 + (((c>>2) ^ (row&7))<<4) + (c&3)*4.
// MODE 0: C=acc; MODE 1: C=silu(aux)*acc; MODE 2: C=acc*rowscale[row]
// GROUPED: blockIdx.z = expert, rows in [off[e], off[e+1]), B += e*N*K
// GATHER:  A row = gidx[global_row]
#define TILE_B 16384                  // 128x32 f32
#define STAGE_B (2 * TILE_B)          // A + B
#define NSTAGE 3
#define SMEM_TOTAL (NSTAGE * STAGE_B) // 96KB

template <int MODE, bool GROUPED, bool GATHER>
__global__ void __launch_bounds__(256, 2)
gemm_cp(const float* __restrict__ A,
        const float* __restrict__ Bb,
        float* __restrict__ C,
        const float* __restrict__ aux,
        const float* __restrict__ rowscale,
        const int* __restrict__ offs,
        const int* __restrict__ gidx,
        int M, int N, int K) {
    extern __shared__ __align__(128) char smem[];

    int rstart, rend;
    const float* B = Bb;
    if (GROUPED) {
        int e = blockIdx.z;
        rstart = offs[e];
        rend = offs[e + 1];
        B += (size_t)e * N * K;
    } else {
        rstart = 0;
        rend = M;
    }
    int rowBase = rstart + blockIdx.y * 128;
    if (rowBase >= rend) return;
    int colBase = blockIdx.x * 128;

    uint32_t sb = smem_u32(smem);
    int tid = threadIdx.x;
    int wid = tid >> 5, lane = tid & 31;
    int warp_m = wid & 1;     // 2 warps over M (64 rows)
    int warp_n = wid >> 1;    // 4 warps over N (32 cols)
    int g = lane >> 2, tg = lane & 3;

    // loader assignments: 4 16B chunks per thread per tile
    int lrow[4], lc4[4], aidx[4];
    uint32_t soff[4], asz[4];
    #pragma unroll
    for (int j = 0; j < 4; j++) {
        int f = tid + j * 256;
        lrow[j] = f >> 3;
        lc4[j] = f & 7;
        soff[j] = (uint32_t)(lrow[j] * 128 + ((lc4[j] ^ (lrow[j] & 7)) << 4));
        int grow = rowBase + lrow[j];
        bool v = (grow < rend);
        asz[j] = v ? 16u : 0u;
        aidx[j] = v ? (GATHER ? gidx[grow] : grow) : 0;
    }

    // ldmatrix address components (verified R5 mapping)
    int la7 = lane & 7;
    int lav = lane >> 4;              // A: k-chunk +1 selector
    int bhi = (lane >> 3) & 1;        // B: k-chunk selector
    uint32_t a_row0 = (uint32_t)(warp_m * 64 + la7 + (((lane >> 3) & 1) ? 8 : 0));
    uint32_t b_row0 = (uint32_t)(warp_n * 32 + la7);

    float acc[4][4][4];
    #pragma unroll
    for (int mt = 0; mt < 4; mt++)
        #pragma unroll
        for (int nt = 0; nt < 4; nt++)
            #pragma unroll
            for (int r = 0; r < 4; r++) acc[mt][nt][r] = 0.f;

    int NC = K / 32;

    // issue one chunk's copies into a stage
    auto issue = [&](int stage, int k0) {
        uint32_t abase = sb + stage * STAGE_B;
        uint32_t bbase = abase + TILE_B;
        #pragma unroll
        for (int j = 0; j < 4; j++) {
            const float* src = A + (size_t)aidx[j] * K + k0 + lc4[j] * 4;
            CP_ASYNC16(abase + soff[j], src, asz[j]);
        }
        #pragma unroll
        for (int j = 0; j < 4; j++) {
            const float* src = B + (size_t)(colBase + lrow[j]) * K + k0 + lc4[j] * 4;
            CP_ASYNC16(bbase + soff[j], src, 16u);
        }
    };

    // prologue: stages 0, 1
    issue(0, 0);
    CP_COMMIT();
    if (NC > 1) issue(1, 32);
    CP_COMMIT();

    for (int i = 0; i < NC; i++) {
        CP_WAIT1();          // chunk i resident
        __syncthreads();     // fences prior reads of the stage about to be overwritten
        if (i + 2 < NC) issue((i + 2) % NSTAGE, (i + 2) * 32);
        CP_COMMIT();

        uint32_t abase = sb + (i % NSTAGE) * STAGE_B;
        uint32_t bbase = abase + TILE_B;
        #pragma unroll
        for (int ks = 0; ks < 4; ks++) {
            uint32_t af[4][4], bf[4][2];
            #pragma unroll
            for (int mt = 0; mt < 4; mt++) {
                uint32_t addr = abase + (a_row0 + mt * 16) * 128 +
                                ((uint32_t)((ks * 2 + lav) ^ la7) << 4);
                LDSM_X4(af[mt], addr);
                #pragma unroll
                for (int q = 0; q < 4; q++) af[mt][q] = f2tf32(af[mt][q]);
            }
            #pragma unroll
            for (int nt = 0; nt < 4; nt++) {
                uint32_t addr = bbase + (b_row0 + (uint32_t)(nt * 8)) * 128 +
                                ((uint32_t)((ks * 2 + bhi) ^ la7) << 4);
                LDSM_X2(bf[nt], addr);
                bf[nt][0] = f2tf32(bf[nt][0]);
                bf[nt][1] = f2tf32(bf[nt][1]);
            }
            #pragma unroll
            for (int mt = 0; mt < 4; mt++)
                #pragma unroll
                for (int nt = 0; nt < 4; nt++)
                    mma_tf32(acc[mt][nt], af[mt], bf[nt]);
        }
    }

    // epilogue: fragment -> float2 stores
    #pragma unroll
    for (int mt = 0; mt < 4; mt++) {
        #pragma unroll
        for (int half = 0; half < 2; half++) {
            int grow = rowBase + warp_m * 64 + mt * 16 + g + half * 8;
            if (grow >= rend) continue;
            float rs = (MODE == 2) ? rowscale[grow] : 0.f;
            #pragma unroll
            for (int nt = 0; nt < 4; nt++) {
                int col = colBase + warp_n * 32 + nt * 8 + tg * 2;
                size_t idx = (size_t)grow * N + col;
                float v0 = acc[mt][nt][half * 2 + 0];
                float v1 = acc[mt][nt][half * 2 + 1];
                float2 r;
                if (MODE == 0) {
                    r = make_float2(v0, v1);
                } else if (MODE == 1) {
                    float2 gg = *reinterpret_cast<const float2*>(aux + idx);
                    float s0 = gg.x / (1.f + __expf(-gg.x));
                    float s1 = gg.y / (1.f + __expf(-gg.y));
                    r = make_float2(s0 * v0, s1 * v1);
                } else {
                    r = make_float2(rs * v0, rs * v1);
                }
                *reinterpret_cast<float2*>(C + idx) = r;
            }
        }
    }
}

// ---------------- combine ----------------
__global__ void combine_kernel(float* __restrict__ out) {
    int t = blockIdx.x;
    int i = threadIdx.x;  // 0..511 (H/4)
    int p0 = g_tokpair[2 * t + 0];
    int p1 = g_tokpair[2 * t + 1];
    float ct = g_c[t];
    const float4* b4 = reinterpret_cast<const float4*>(g_base) + (size_t)t * (HDIM / 4);
    const float4* q0 = reinterpret_cast<const float4*>(g_pout) + (size_t)p0 * (HDIM / 4);
    const float4* q1 = reinterpret_cast<const float4*>(g_pout) + (size_t)p1 * (HDIM / 4);
    float4 b = b4[i], a0 = q0[i], a1 = q1[i];
    float4 r;
    r.x = ct * b.x + a0.x + a1.x;
    r.y = ct * b.y + a0.y + a1.y;
    r.z = ct * b.z + a0.z + a1.z;
    r.w = ct * b.w + a0.w + a1.w;
    reinterpret_cast<float4*>(out)[(size_t)t * (HDIM / 4) + i] = r;
}

// ---------------- launch ----------------
extern "C" void kernel_launch(void* const* d_in, const int* in_sizes, int n_in,
                              void* d_out, int out_size) {
    const float* x   = (const float*)d_in[0];
    const float* wg  = (const float*)d_in[1];
    const float* wu  = (const float*)d_in[2];
    const float* wd  = (const float*)d_in[3];
    const float* rw  = (const float*)d_in[4];
    const float* weg = (const float*)d_in[5];
    const float* weu = (const float*)d_in[6];
    const float* wed = (const float*)d_in[7];
    const float* alp = (const float*)d_in[8];
    float* out = (float*)d_out;

    float *pG, *pHb, *pBase, *pEG, *pHE, *pPout, *pPairw;
    int *pOff, *pPairtok;
    cudaGetSymbolAddress((void**)&pG, g_G);
    cudaGetSymbolAddress((void**)&pHb, g_Hb);
    cudaGetSymbolAddress((void**)&pBase, g_base);
    cudaGetSymbolAddress((void**)&pEG, g_EG);
    cudaGetSymbolAddress((void**)&pHE, g_HE);
    cudaGetSymbolAddress((void**)&pPout, g_pout);
    cudaGetSymbolAddress((void**)&pPairw, g_pairw);
    cudaGetSymbolAddress((void**)&pOff, g_off);
    cudaGetSymbolAddress((void**)&pPairtok, g_pairtok);

    cudaFuncSetAttribute(gemm_cp<0, false, false>, cudaFuncAttributeMaxDynamicSharedMemorySize, SMEM_TOTAL);
    cudaFuncSetAttribute(gemm_cp<1, false, false>, cudaFuncAttributeMaxDynamicSharedMemorySize, SMEM_TOTAL);
    cudaFuncSetAttribute(gemm_cp<0, true, true>,  cudaFuncAttributeMaxDynamicSharedMemorySize, SMEM_TOTAL);
    cudaFuncSetAttribute(gemm_cp<1, true, true>,  cudaFuncAttributeMaxDynamicSharedMemorySize, SMEM_TOTAL);
    cudaFuncSetAttribute(gemm_cp<2, true, false>, cudaFuncAttributeMaxDynamicSharedMemorySize, SMEM_TOTAL);

    // 1) routing (fp32-exact)
    zero_counts_kernel<<<1, 32>>>();
    router_kernel<<<T_TOK, 256>>>(x, rw, alp);
    scan_kernel<<<1, 1>>>();
    scatter_kernel<<<T_TOK / 256, 256>>>();

    // 2) base MLP
    dim3 gBaseFF(FB / 128, T_TOK / 128, 1);
    gemm_cp<0, false, false><<<gBaseFF, 256, SMEM_TOTAL>>>(x, wg, pG, nullptr, nullptr, nullptr, nullptr,
                                                           T_TOK, FB, HDIM);
    gemm_cp<1, false, false><<<gBaseFF, 256, SMEM_TOTAL>>>(x, wu, pHb, pG, nullptr, nullptr, nullptr,
                                                           T_TOK, FB, HDIM);
    dim3 gBaseDown(HDIM / 128, T_TOK / 128, 1);
    gemm_cp<0, false, false><<<gBaseDown, 256, SMEM_TOTAL>>>(pHb, wd, pBase, nullptr, nullptr, nullptr, nullptr,
                                                             T_TOK, HDIM, FB);

    // 3) expert MLPs (grouped, gathered)
    dim3 gExpFF(FE / 128, 16, NE);
    gemm_cp<0, true, true><<<gExpFF, 256, SMEM_TOTAL>>>(x, weg, pEG, nullptr, nullptr, pOff, pPairtok,
                                                        NPAIR, FE, HDIM);
    gemm_cp<1, true, true><<<gExpFF, 256, SMEM_TOTAL>>>(x, weu, pHE, pEG, nullptr, pOff, pPairtok,
                                                        NPAIR, FE, HDIM);
    dim3 gExpDown(HDIM / 128, 16, NE);
    gemm_cp<2, true, false><<<gExpDown, 256, SMEM_TOTAL>>>(pHE, wed, pPout, nullptr, pPairw, pOff, nullptr,
                                                           NPAIR, HDIM, FE);

    // 4) combine
    combine_kernel<<<T_TOK, HDIM / 4>>>(out);
}

// round 7
// speedup vs baseline: 1.5498x; 1.1504x over previous
#include <cuda_runtime.h>
#include <math.h>
#include <stdint.h>

// ---------------- problem constants ----------------
#define T_TOK 2048
#define HDIM  2048
#define FB    8192
#define NE    8
#define FE    1024
#define TOPK  2
#define NPAIR (T_TOK * TOPK)

// ---------------- scratch ----------------
__device__ float g_G   [(size_t)T_TOK * FB];
__device__ float g_Hb  [(size_t)T_TOK * FB];     // tf32-rounded (fed to down GEMM)
__device__ float g_base[(size_t)T_TOK * HDIM];
__device__ float g_EG  [(size_t)NPAIR * FE];
__device__ float g_HE  [(size_t)NPAIR * FE];     // tf32-rounded
__device__ float g_pout[(size_t)NPAIR * HDIM];
__device__ int   g_cnt[NE];
__device__ int   g_off[NE + 1];
__device__ int   g_cur[NE];
__device__ int   g_tokexp[T_TOK * TOPK];
__device__ float g_tokw  [T_TOK * TOPK];
__device__ int   g_pairtok[NPAIR];
__device__ float g_pairw  [NPAIR];
__device__ int   g_tokpair[T_TOK * TOPK];
__device__ float g_c[T_TOK];

// tf32-preconverted operands
__device__ float g_xc  [(size_t)T_TOK * HDIM];
__device__ float g_wgc [(size_t)FB * HDIM];
__device__ float g_wuc [(size_t)FB * HDIM];
__device__ float g_wdc [(size_t)HDIM * FB];
__device__ float g_wegc[(size_t)NE * FE * HDIM];
__device__ float g_weuc[(size_t)NE * FE * HDIM];
__device__ float g_wedc[(size_t)NE * HDIM * FE];

// ---------------- helpers ----------------
__device__ __forceinline__ uint32_t smem_u32(const void* p) {
    uint32_t a;
    asm("{ .reg .u64 t; cvta.to.shared.u64 t, %1; cvt.u32.u64 %0, t; }" : "=r"(a) : "l"(p));
    return a;
}
__device__ __forceinline__ float tf32r(float f) {
    uint32_t u;
    asm("cvt.rna.tf32.f32 %0, %1;" : "=r"(u) : "f"(f));
    return __uint_as_float(u);
}
__device__ __forceinline__ void mma_tf32(float c[4], const uint32_t a[4], const uint32_t b[2]) {
    asm volatile(
        "mma.sync.aligned.m16n8k8.row.col.f32.tf32.tf32.f32 "
        "{%0,%1,%2,%3}, {%4,%5,%6,%7}, {%8,%9}, {%0,%1,%2,%3};\n"
        : "+f"(c[0]), "+f"(c[1]), "+f"(c[2]), "+f"(c[3])
        : "r"(a[0]), "r"(a[1]), "r"(a[2]), "r"(a[3]), "r"(b[0]), "r"(b[1]));
}
#define LDSM_X4(r, addr) \
    asm volatile("ldmatrix.sync.aligned.m8n8.x4.shared.b16 {%0,%1,%2,%3}, [%4];" \
        : "=r"((r)[0]), "=r"((r)[1]), "=r"((r)[2]), "=r"((r)[3]) : "r"(addr))
#define CP_ASYNC16(dst, src, sz) \
    asm volatile("cp.async.cg.shared.global [%0], [%1], 16, %2;" \
        :: "r"(dst), "l"(src), "r"(sz) : "memory")
#define CP_COMMIT() asm volatile("cp.async.commit_group;" ::: "memory")
#define CP_WAIT1()  asm volatile("cp.async.wait_group 1;" ::: "memory")

// ---------------- conversion prepass: dst = tf32_round(src), float4 granularity ----
__global__ void cvt_tf32_kernel(const float* __restrict__ src, float* __restrict__ dst, int n4) {
    int i = blockIdx.x * blockDim.x + threadIdx.x;
    int stride = gridDim.x * blockDim.x;
    for (; i < n4; i += stride) {
        float4 v = reinterpret_cast<const float4*>(src)[i];
        v.x = tf32r(v.x); v.y = tf32r(v.y); v.z = tf32r(v.z); v.w = tf32r(v.w);
        reinterpret_cast<float4*>(dst)[i] = v;
    }
}

// ---------------- small kernels (fp32-exact routing) ----------------
__global__ void zero_counts_kernel() {
    int i = threadIdx.x;
    if (i < NE) g_cnt[i] = 0;
}

__global__ void router_kernel(const float* __restrict__ x,
                              const float* __restrict__ rw,
                              const float* __restrict__ alpha) {
    int t = blockIdx.x;
    int tid = threadIdx.x;
    int w = tid >> 5;
    int lane = tid & 31;
    __shared__ float lg[NE];

    float s = 0.f;
    const float* xr = x + (size_t)t * HDIM;
    const float* wr = rw + (size_t)w * HDIM;
    for (int h = lane; h < HDIM; h += 32) s += xr[h] * wr[h];
    #pragma unroll
    for (int o = 16; o > 0; o >>= 1) s += __shfl_down_sync(0xffffffffu, s, o);
    if (lane == 0) lg[w] = s;
    __syncthreads();

    if (tid == 0) {
        float v0 = -1e30f, v1 = -1e30f;
        int i0 = 0, i1 = 0;
        #pragma unroll
        for (int e = 0; e < NE; e++) {
            float v = lg[e];
            if (v > v0) { v1 = v0; i1 = i0; v0 = v; i0 = e; }
            else if (v > v1) { v1 = v; i1 = e; }
        }
        float e1 = expf(v1 - v0);
        float inv = 1.f / (1.f + e1);
        float wa0 = inv * alpha[i0];
        float wa1 = e1 * inv * alpha[i1];
        g_tokexp[2 * t + 0] = i0;
        g_tokexp[2 * t + 1] = i1;
        g_tokw[2 * t + 0] = wa0;
        g_tokw[2 * t + 1] = wa1;
        g_c[t] = 1.f - wa0 - wa1;
        atomicAdd(&g_cnt[i0], 1);
        atomicAdd(&g_cnt[i1], 1);
    }
}

__global__ void scan_kernel() {
    if (threadIdx.x == 0) {
        int acc = 0;
        for (int e = 0; e < NE; e++) {
            g_off[e] = acc;
            g_cur[e] = acc;
            acc += g_cnt[e];
        }
        g_off[NE] = acc;
    }
}

__global__ void scatter_kernel() {
    int t = blockIdx.x * blockDim.x + threadIdx.x;
    if (t >= T_TOK) return;
    #pragma unroll
    for (int s = 0; s < TOPK; s++) {
        int e = g_tokexp[2 * t + s];
        int pos = atomicAdd(&g_cur[e], 1);
        g_pairtok[pos] = t;
        g_pairw[pos] = g_tokw[2 * t + s];
        g_tokpair[2 * t + s] = pos;
    }
}

// ---------------- cp.async 3-stage tf32 GEMM (operands pre-rounded; no mainloop cvt)
// C[m,n] = sum_k A[m,k]*B[n,k]; tile BM=BN=128, BK=32, 128B rows, swizzled.
// Swizzle: elem(row, c) at byte row*128 + (((c>>2) ^ (row&7))<<4) + (c&3)*4.
// MODE 0: C=acc; MODE 1: C=silu(aux)*acc; MODE 2: C=acc*rowscale[row]
// RND: round output to tf32 (for intermediates feeding another GEMM)
#define TILE_B 16384
#define STAGE_B (2 * TILE_B)
#define NSTAGE 3
#define SMEM_TOTAL (NSTAGE * STAGE_B) // 96KB

template <int MODE, bool GROUPED, bool GATHER, bool RND>
__global__ void __launch_bounds__(256, 2)
gemm_cp(const float* __restrict__ A,
        const float* __restrict__ Bb,
        float* __restrict__ C,
        const float* __restrict__ aux,
        const float* __restrict__ rowscale,
        const int* __restrict__ offs,
        const int* __restrict__ gidx,
        int M, int N, int K) {
    extern __shared__ __align__(128) char smem[];

    int rstart, rend;
    const float* B = Bb;
    if (GROUPED) {
        int e = blockIdx.z;
        rstart = offs[e];
        rend = offs[e + 1];
        B += (size_t)e * N * K;
    } else {
        rstart = 0;
        rend = M;
    }
    int rowBase = rstart + blockIdx.y * 128;
    if (rowBase >= rend) return;
    int colBase = blockIdx.x * 128;

    uint32_t sb = smem_u32(smem);
    int tid = threadIdx.x;
    int wid = tid >> 5, lane = tid & 31;
    int warp_m = wid & 1;     // 2 warps over M (64 rows)
    int warp_n = wid >> 1;    // 4 warps over N (32 cols)
    int g = lane >> 2, tg = lane & 3;

    // loader assignments: 4 16B chunks per thread per tile
    int lrow[4], lc4[4], aidx[4];
    uint32_t soff[4], asz[4];
    #pragma unroll
    for (int j = 0; j < 4; j++) {
        int f = tid + j * 256;
        lrow[j] = f >> 3;
        lc4[j] = f & 7;
        soff[j] = (uint32_t)(lrow[j] * 128 + ((lc4[j] ^ (lrow[j] & 7)) << 4));
        int grow = rowBase + lrow[j];
        bool v = (grow < rend);
        asz[j] = v ? 16u : 0u;
        aidx[j] = v ? (GATHER ? gidx[grow] : grow) : 0;
    }

    // ldmatrix address components (verified mapping)
    int la7 = lane & 7;
    int lav = lane >> 4;              // A: k-chunk selector (x4: matrices 0,1 chunk0; 2,3 chunk1)
    int bhi = (lane >> 3) & 1;        // B: k-chunk selector within pair
    int bnadd = (lane >> 4) * 8;      // B: +8 n-rows for matrices 2,3
    uint32_t a_row0 = (uint32_t)(warp_m * 64 + la7 + (((lane >> 3) & 1) ? 8 : 0));
    uint32_t b_row0 = (uint32_t)(warp_n * 32 + bnadd + la7);

    float acc[4][4][4];
    #pragma unroll
    for (int mt = 0; mt < 4; mt++)
        #pragma unroll
        for (int nt = 0; nt < 4; nt++)
            #pragma unroll
            for (int r = 0; r < 4; r++) acc[mt][nt][r] = 0.f;

    int NC = K / 32;

    auto issue = [&](int stage, int k0) {
        uint32_t abase = sb + stage * STAGE_B;
        uint32_t bbase = abase + TILE_B;
        #pragma unroll
        for (int j = 0; j < 4; j++) {
            const float* src = A + (size_t)aidx[j] * K + k0 + lc4[j] * 4;
            CP_ASYNC16(abase + soff[j], src, asz[j]);
        }
        #pragma unroll
        for (int j = 0; j < 4; j++) {
            const float* src = B + (size_t)(colBase + lrow[j]) * K + k0 + lc4[j] * 4;
            CP_ASYNC16(bbase + soff[j], src, 16u);
        }
    };

    issue(0, 0);
    CP_COMMIT();
    if (NC > 1) issue(1, 32);
    CP_COMMIT();

    for (int i = 0; i < NC; i++) {
        CP_WAIT1();
        __syncthreads();
        if (i + 2 < NC) issue((i + 2) % NSTAGE, (i + 2) * 32);
        CP_COMMIT();

        uint32_t abase = sb + (i % NSTAGE) * STAGE_B;
        uint32_t bbase = abase + TILE_B;
        #pragma unroll
        for (int ks = 0; ks < 4; ks++) {
            uint32_t af[4][4], bf2[2][4];
            #pragma unroll
            for (int mt = 0; mt < 4; mt++) {
                uint32_t addr = abase + (a_row0 + mt * 16) * 128 +
                                ((uint32_t)((ks * 2 + lav) ^ la7) << 4);
                LDSM_X4(af[mt], addr);
            }
            // B: one x4 covers two nt tiles (16 n-rows x both k-chunks)
            #pragma unroll
            for (int np = 0; np < 2; np++) {
                uint32_t addr = bbase + (b_row0 + (uint32_t)(np * 16)) * 128 +
                                ((uint32_t)((ks * 2 + bhi) ^ la7) << 4);
                LDSM_X4(bf2[np], addr);
            }
            #pragma unroll
            for (int mt = 0; mt < 4; mt++)
                #pragma unroll
                for (int nt = 0; nt < 4; nt++)
                    mma_tf32(acc[mt][nt], af[mt], &bf2[nt >> 1][(nt & 1) * 2]);
        }
    }

    // epilogue: fragment -> float2 stores
    #pragma unroll
    for (int mt = 0; mt < 4; mt++) {
        #pragma unroll
        for (int half = 0; half < 2; half++) {
            int grow = rowBase + warp_m * 64 + mt * 16 + g + half * 8;
            if (grow >= rend) continue;
            float rs = (MODE == 2) ? rowscale[grow] : 0.f;
            #pragma unroll
            for (int nt = 0; nt < 4; nt++) {
                int col = colBase + warp_n * 32 + nt * 8 + tg * 2;
                size_t idx = (size_t)grow * N + col;
                float v0 = acc[mt][nt][half * 2 + 0];
                float v1 = acc[mt][nt][half * 2 + 1];
                float2 r;
                if (MODE == 0) {
                    r = make_float2(v0, v1);
                } else if (MODE == 1) {
                    float2 gg = *reinterpret_cast<const float2*>(aux + idx);
                    float s0 = gg.x / (1.f + __expf(-gg.x));
                    float s1 = gg.y / (1.f + __expf(-gg.y));
                    r = make_float2(s0 * v0, s1 * v1);
                } else {
                    r = make_float2(rs * v0, rs * v1);
                }
                if (RND) { r.x = tf32r(r.x); r.y = tf32r(r.y); }
                *reinterpret_cast<float2*>(C + idx) = r;
            }
        }
    }
}

// ---------------- combine ----------------
__global__ void combine_kernel(float* __restrict__ out) {
    int t = blockIdx.x;
    int i = threadIdx.x;  // 0..511 (H/4)
    int p0 = g_tokpair[2 * t + 0];
    int p1 = g_tokpair[2 * t + 1];
    float ct = g_c[t];
    const float4* b4 = reinterpret_cast<const float4*>(g_base) + (size_t)t * (HDIM / 4);
    const float4* q0 = reinterpret_cast<const float4*>(g_pout) + (size_t)p0 * (HDIM / 4);
    const float4* q1 = reinterpret_cast<const float4*>(g_pout) + (size_t)p1 * (HDIM / 4);
    float4 b = b4[i], a0 = q0[i], a1 = q1[i];
    float4 r;
    r.x = ct * b.x + a0.x + a1.x;
    r.y = ct * b.y + a0.y + a1.y;
    r.z = ct * b.z + a0.z + a1.z;
    r.w = ct * b.w + a0.w + a1.w;
    reinterpret_cast<float4*>(out)[(size_t)t * (HDIM / 4) + i] = r;
}

// ---------------- launch ----------------
extern "C" void kernel_launch(void* const* d_in, const int* in_sizes, int n_in,
                              void* d_out, int out_size) {
    const float* x   = (const float*)d_in[0];
    const float* wg  = (const float*)d_in[1];
    const float* wu  = (const float*)d_in[2];
    const float* wd  = (const float*)d_in[3];
    const float* rw  = (const float*)d_in[4];
    const float* weg = (const float*)d_in[5];
    const float* weu = (const float*)d_in[6];
    const float* wed = (const float*)d_in[7];
    const float* alp = (const float*)d_in[8];
    float* out = (float*)d_out;

    float *pG, *pHb, *pBase, *pEG, *pHE, *pPout, *pPairw;
    float *pXc, *pWgc, *pWuc, *pWdc, *pWegc, *pWeuc, *pWedc;
    int *pOff, *pPairtok;
    cudaGetSymbolAddress((void**)&pG, g_G);
    cudaGetSymbolAddress((void**)&pHb, g_Hb);
    cudaGetSymbolAddress((void**)&pBase, g_base);
    cudaGetSymbolAddress((void**)&pEG, g_EG);
    cudaGetSymbolAddress((void**)&pHE, g_HE);
    cudaGetSymbolAddress((void**)&pPout, g_pout);
    cudaGetSymbolAddress((void**)&pPairw, g_pairw);
    cudaGetSymbolAddress((void**)&pOff, g_off);
    cudaGetSymbolAddress((void**)&pPairtok, g_pairtok);
    cudaGetSymbolAddress((void**)&pXc, g_xc);
    cudaGetSymbolAddress((void**)&pWgc, g_wgc);
    cudaGetSymbolAddress((void**)&pWuc, g_wuc);
    cudaGetSymbolAddress((void**)&pWdc, g_wdc);
    cudaGetSymbolAddress((void**)&pWegc, g_wegc);
    cudaGetSymbolAddress((void**)&pWeuc, g_weuc);
    cudaGetSymbolAddress((void**)&pWedc, g_wedc);

    cudaFuncSetAttribute(gemm_cp<0, false, false, false>, cudaFuncAttributeMaxDynamicSharedMemorySize, SMEM_TOTAL);
    cudaFuncSetAttribute(gemm_cp<1, false, false, true>,  cudaFuncAttributeMaxDynamicSharedMemorySize, SMEM_TOTAL);
    cudaFuncSetAttribute(gemm_cp<0, true, true, false>,   cudaFuncAttributeMaxDynamicSharedMemorySize, SMEM_TOTAL);
    cudaFuncSetAttribute(gemm_cp<1, true, true, true>,    cudaFuncAttributeMaxDynamicSharedMemorySize, SMEM_TOTAL);
    cudaFuncSetAttribute(gemm_cp<2, true, false, false>,  cudaFuncAttributeMaxDynamicSharedMemorySize, SMEM_TOTAL);

    // 0) tf32 prepass (dominates prepass time: ~420MB; grid-stride)
    const int CVT_GRID = 1184, CVT_BLK = 256;
    cvt_tf32_kernel<<<CVT_GRID, CVT_BLK>>>(x,   pXc,  (T_TOK * HDIM) / 4);
    cvt_tf32_kernel<<<CVT_GRID, CVT_BLK>>>(wg,  pWgc, (FB * HDIM) / 4);
    cvt_tf32_kernel<<<CVT_GRID, CVT_BLK>>>(wu,  pWuc, (FB * HDIM) / 4);
    cvt_tf32_kernel<<<CVT_GRID, CVT_BLK>>>(wd,  pWdc, (HDIM * FB) / 4);
    cvt_tf32_kernel<<<CVT_GRID, CVT_BLK>>>(weg, pWegc, (NE * FE * HDIM) / 4);
    cvt_tf32_kernel<<<CVT_GRID, CVT_BLK>>>(weu, pWeuc, (NE * FE * HDIM) / 4);
    cvt_tf32_kernel<<<CVT_GRID, CVT_BLK>>>(wed, pWedc, (NE * HDIM * FE) / 4);

    // 1) routing (fp32-exact, uses original x)
    zero_counts_kernel<<<1, 32>>>();
    router_kernel<<<T_TOK, 256>>>(x, rw, alp);
    scan_kernel<<<1, 1>>>();
    scatter_kernel<<<T_TOK / 256, 256>>>();

    // 2) base MLP
    dim3 gBaseFF(FB / 128, T_TOK / 128, 1);
    gemm_cp<0, false, false, false><<<gBaseFF, 256, SMEM_TOTAL>>>(pXc, pWgc, pG, nullptr, nullptr, nullptr, nullptr,
                                                                  T_TOK, FB, HDIM);
    gemm_cp<1, false, false, true><<<gBaseFF, 256, SMEM_TOTAL>>>(pXc, pWuc, pHb, pG, nullptr, nullptr, nullptr,
                                                                 T_TOK, FB, HDIM);
    dim3 gBaseDown(HDIM / 128, T_TOK / 128, 1);
    gemm_cp<0, false, false, false><<<gBaseDown, 256, SMEM_TOTAL>>>(pHb, pWdc, pBase, nullptr, nullptr, nullptr, nullptr,
                                                                    T_TOK, HDIM, FB);

    // 3) expert MLPs (grouped, gathered)
    dim3 gExpFF(FE / 128, 16, NE);
    gemm_cp<0, true, true, false><<<gExpFF, 256, SMEM_TOTAL>>>(pXc, pWegc, pEG, nullptr, nullptr, pOff, pPairtok,
                                                               NPAIR, FE, HDIM);
    gemm_cp<1, true, true, true><<<gExpFF, 256, SMEM_TOTAL>>>(pXc, pWeuc, pHE, pEG, nullptr, pOff, pPairtok,
                                                              NPAIR, FE, HDIM);
    dim3 gExpDown(HDIM / 128, 16, NE);
    gemm_cp<2, true, false, false><<<gExpDown, 256, SMEM_TOTAL>>>(pHE, pWedc, pPout, nullptr, pPairw, pOff, nullptr,
                                                                  NPAIR, HDIM, FE);

    // 4) combine
    combine_kernel<<<T_TOK, HDIM / 4>>>(out);
}